// round 7
// baseline (speedup 1.0000x reference)
#include <cuda_runtime.h>
#include <math.h>
#include <mma.h>
using namespace nvcuda;

#define LL 16
#define CC 32
#define HH 64
#define WW 64
#define WF 33
#define RR 16

// ---------------- scratch (device globals; no allocs allowed) ----------------
__device__ float d_f1[LL*CC*HH*WW];     // conv1 out (l,c,h,w)
__device__ float d_f2[LL*CC*HH*WW];     // conv2 out (l,c,h,w)
__device__ float d_cmean[LL*CC];        // per (l,c) spatial mean of f2
__device__ float d_cs[LL*CC*WW];        // per (l,c) column sums over h
__device__ float d_Are[LL*CC*WF*RR];
__device__ float d_Aim[LL*CC*WF*RR];
__device__ float d_S  [LL*CC*WF*RR];
__device__ float d_xfr[LL*CC*WF*HH];    // rfft(x); overwritten in-place by scanmix
__device__ float d_xfi[LL*CC*WF*HH];
__device__ float d_y2 [LL*CC*HH*WW];    // pif-mixed spatial output
__device__ float d_mu[LL*4];
__device__ float d_rstd[LL*4];
__device__ float d_psum[LL*CC];
__device__ float d_psq [LL*CC];
__device__ float d_ymean[LL*CC*HH];     // raw mean over w of y2
__device__ float d_gate[LL*CC*HH];      // (l,c,h)
__device__ float d_wr[CC];
__device__ float d_wi[CC];
__device__ float d_br;
__device__ float d_bi;

__device__ __forceinline__ float fsigmoid(float x) {
    return 1.f / (1.f + __expf(-x));
}
__device__ __forceinline__ float fsilu(float x) {
    return x / (1.f + __expf(-x));
}

// ---------------- prep: collapse mix/rank_scale/proj into 64-weight dot ------
__global__ void k_prep(const float* __restrict__ mix_w, const float* __restrict__ mix_b,
                       const float* __restrict__ rs, const float* __restrict__ pw,
                       const float* __restrict__ pb)
{
    int j = threadIdx.x;  // 0..31
    float swr = 0.f, swi = 0.f;
    for (int r = 0; r < RR; r++) {
        float a = rs[r] * pw[r];
        swr += a * mix_w[r*32 + j];
        swi += a * mix_w[(16+r)*32 + j];
    }
    d_wr[j] = swr; d_wi[j] = swi;
    if (j == 0) {
        float br = pb[0], bi = 0.f;
        for (int r = 0; r < RR; r++) {
            float a = rs[r] * pw[r];
            br += a * mix_b[r];
            bi += a * mix_b[16+r];
        }
        d_br = br; d_bi = bi;
    }
}

// ---------------- conv 3x3 SAME + silu via TF32 tensor cores -----------------
// Implicit GEMM per l: out[m,n] = sum_k A[m,k]*W[n,k], m=h*64+w, n=co,
// k = ci*16 + tap (taps 0..8 real, 9..15 zero-padded).
// grid (32 m-tiles of 128, 16 l), block 256 (8 warps).
// Warp w: m rows [w*16, w*16+16) of the 128-row block tile, both n16 halves.
// Dynamic smem: Bs[32*16*32] | region{ As[128*20] / Cs[8*16*36] }.
#define CONV_SMEM_FLOATS (32*16*32 + 8*16*36)
#define CONV_SMEM_BYTES  (CONV_SMEM_FLOATS*4)

__device__ __forceinline__ void convtc_body(const float* __restrict__ in, int in_base,
                                            int cstride,
                                            const float* __restrict__ wgt,
                                            const float* __restrict__ bias,
                                            float* __restrict__ out, int l)
{
    extern __shared__ float smem[];
    float* Bs = smem;                 // [ci][k16][n32] : 16384 floats
    float* As = smem + 16384;         // [m128][20]     : 2560 floats
    float* Cs = smem + 16384;         // epilogue reuse : 8*16*36 floats

    int tid = threadIdx.x;
    int warp = tid >> 5, lane = tid & 31;
    int mt = blockIdx.x;              // 0..31 (2 h-rows each)
    int h0 = mt * 2;

    // preload weights, zero-pad taps 9..15
    for (int i = tid; i < 32*16*32; i += 256) {
        int ci = i >> 9, k = (i >> 5) & 15, n = i & 31;
        Bs[i] = (k < 9) ? wgt[n*288 + ci*9 + k] : 0.f;
    }
    // zero A (pad columns 9..19 stay zero forever)
    for (int i = tid; i < 128*20; i += 256) As[i] = 0.f;

    wmma::fragment<wmma::accumulator, 16, 16, 8, float> c0, c1;
    wmma::fill_fragment(c0, 0.f);
    wmma::fill_fragment(c1, 0.f);

    const float* inb = in + in_base;
    for (int ci = 0; ci < 32; ci++) {
        __syncthreads();   // previous iter's frag loads done before rewriting As
        // im2col fill, k-major for coalesced gmem reads (1152 = 9 taps x 128 m)
        const float* cin = inb + ci * cstride;
        for (int i = tid; i < 1152; i += 256) {
            int k = i >> 7, m = i & 127;
            int dy = k / 3, dx = k - dy*3;
            int hh = m >> 6, w = m & 63;
            int gh = h0 + hh - 1 + dy;
            int gw = w - 1 + dx;
            float v = 0.f;
            if (gh >= 0 && gh < 64 && gw >= 0 && gw < 64)
                v = cin[gh*64 + gw];
            As[m*20 + k] = v;
        }
        __syncthreads();
        #pragma unroll
        for (int kc = 0; kc < 2; kc++) {
            wmma::fragment<wmma::matrix_a, 16, 16, 8, wmma::precision::tf32, wmma::row_major> a;
            wmma::fragment<wmma::matrix_b, 16, 16, 8, wmma::precision::tf32, wmma::row_major> b0, b1;
            wmma::load_matrix_sync(a, &As[warp*16*20 + kc*8], 20);
            #pragma unroll
            for (int t = 0; t < a.num_elements; t++) a.x[t] = wmma::__float_to_tf32(a.x[t]);
            const float* bp = &Bs[(ci*16 + kc*8)*32];
            wmma::load_matrix_sync(b0, bp, 32);
            wmma::load_matrix_sync(b1, bp + 16, 32);
            #pragma unroll
            for (int t = 0; t < b0.num_elements; t++) {
                b0.x[t] = wmma::__float_to_tf32(b0.x[t]);
                b1.x[t] = wmma::__float_to_tf32(b1.x[t]);
            }
            wmma::mma_sync(c0, a, b0, c0);
            wmma::mma_sync(c1, a, b1, c1);
        }
    }
    __syncthreads();   // all frag reads of As done before Cs overwrites it
    wmma::store_matrix_sync(&Cs[warp*576], c0, 36, wmma::mem_row_major);
    wmma::store_matrix_sync(&Cs[warp*576 + 16], c1, 36, wmma::mem_row_major);
    __syncwarp();
    int h  = h0 + (warp >> 2);         // warp m-offset = warp*16 -> hh = warp/4
    int w0 = (warp * 16) & 63;
    for (int i = lane; i < 512; i += 32) {
        int mm = i & 15, n = i >> 4;
        float v = Cs[warp*576 + mm*36 + n] + bias[n];
        out[((l*32 + n)*64 + h)*64 + w0 + mm] = fsilu(v);
    }
}

__global__ void __launch_bounds__(256)
k_conv1(const float* __restrict__ x, const float* __restrict__ w,
        const float* __restrict__ b)
{
    // x layout (c,l,h,w): base = l*4096, channel stride = 16*4096
    convtc_body(x, blockIdx.y * 4096, 16*4096, w, b, d_f1, blockIdx.y);
}
__global__ void __launch_bounds__(256)
k_conv2(const float* __restrict__ w, const float* __restrict__ b)
{
    // f1 layout (l,c,h,w): base = l*32*4096, channel stride = 4096
    convtc_body(d_f1, blockIdx.y * 32 * 4096, 4096, w, b, d_f2, blockIdx.y);
}

// ---------------- fused reductions over f2: channel mean + column sums -------
__global__ void k_sum()
{
    __shared__ float xs[64*65];
    __shared__ float red[8];
    int lc = blockIdx.x, tid = threadIdx.x;
    const float* p = d_f2 + lc*4096;
    float s = 0.f;
    for (int i = tid; i < 4096; i += 256) {
        float v = p[i];
        xs[(i >> 6)*65 + (i & 63)] = v;
        s += v;
    }
    #pragma unroll
    for (int off = 16; off > 0; off >>= 1) s += __shfl_down_sync(0xffffffffu, s, off);
    if ((tid & 31) == 0) red[tid >> 5] = s;
    __syncthreads();
    if (tid == 0) {
        float t = 0.f;
        #pragma unroll
        for (int k = 0; k < 8; k++) t += red[k];
        d_cmean[lc] = t / 4096.f;
    }
    if (tid < 64) {
        float cs = 0.f;
        #pragma unroll 8
        for (int h = 0; h < 64; h++) cs += xs[h*65 + tid];
        d_cs[lc*64 + tid] = cs;
    }
}

// ---------------- glob + adaptive pool + head, fused -------------------------
// grid (3 f-chunks of 11, 16 l), block 512 (thread = (c,r))
__global__ void k_headall(const float* __restrict__ gfc_w, const float* __restrict__ gfc_b,
                          const float* __restrict__ head_w, const float* __restrict__ head_b,
                          const float* __restrict__ dt)
{
    __shared__ float gl[32];
    __shared__ float fl[32];
    int f0 = blockIdx.x * 11, l = blockIdx.y, tid = threadIdx.x;
    if (tid < 32) {
        float a = gfc_b[tid];
        #pragma unroll
        for (int ci = 0; ci < 32; ci++) a += d_cmean[l*32 + ci] * gfc_w[tid*32 + ci];
        gl[tid] = fsigmoid(a);
    }
    float dtl = dt[l];
    int c = tid >> 4, r = tid & 15;
    int k0 = (c*16 + r)*3;
    for (int ff = 0; ff < 11; ff++) {
        int fi = f0 + ff;
        __syncthreads();
        if (tid < 32) {
            int st = (fi*64) / 33;
            int en = ((fi+1)*64 + 32) / 33;
            float s = 0.f;
            for (int k = st; k < en; k++) s += d_cs[(l*32 + tid)*64 + k];
            fl[tid] = gl[tid] * s / (64.f * (float)(en - st));
        }
        __syncthreads();
        float p[3];
        #pragma unroll
        for (int t = 0; t < 3; t++) {
            const float* wrow = head_w + (k0 + t)*32;
            float a = head_b[k0 + t];
            #pragma unroll
            for (int ci = 0; ci < 32; ci++) a += fl[ci] * wrow[ci];
            p[t] = a;
        }
        float nu = (p[0] > 20.f) ? p[0] : log1pf(__expf(p[0]));
        float decay = __expf(-nu * dtl);
        float ang = tanhf(p[1]) * 3.14159265358979323846f * dtl;
        float sa, ca;
        __sincosf(ang, &sa, &ca);
        float sg = fsigmoid(p[2]);
        float g  = 1.f - __expf(-2.f * dtl);
        int idx = ((l*32 + c)*33 + fi)*16 + r;
        d_Are[idx] = decay * ca;
        d_Aim[idx] = decay * sa;
        d_S[idx]   = sg * g;
    }
}

// ---------------- rfft over W (64 -> 33 bins), register-tiled GEMM -----------
__global__ void __launch_bounds__(256) k_rfft(const float* __restrict__ x)
{
    __shared__ float xs[64*65];
    __shared__ float ctw[64*36], stw[64*36];  // [w][f0..32]
    int c = blockIdx.x, l = blockIdx.y, tid = threadIdx.x;
    for (int i = tid; i < 64*33; i += 256) {
        int w = i / 33, f = i % 33;
        float sa, ca;
        sincospif((float)((w*f) & 63) / 32.f, &sa, &ca);
        ctw[w*36 + f] = ca; stw[w*36 + f] = sa;
    }
    const float* p = x + (size_t)(c*16 + l)*4096;
    for (int i = tid; i < 4096; i += 256) xs[(i >> 6)*65 + (i & 63)] = p[i];
    __syncthreads();
    int obase = ((l*32 + c)*33)*64;
    if (tid < 128) {
        int hg = tid >> 3, fg = tid & 7;
        int h0 = hg*4, f0 = fg*4;
        float re[4][4], im[4][4];
        #pragma unroll
        for (int j = 0; j < 4; j++)
            #pragma unroll
            for (int k = 0; k < 4; k++) { re[j][k] = 0.f; im[j][k] = 0.f; }
        for (int w = 0; w < 64; w++) {
            float a0 = xs[(h0+0)*65 + w];
            float a1 = xs[(h0+1)*65 + w];
            float a2 = xs[(h0+2)*65 + w];
            float a3 = xs[(h0+3)*65 + w];
            float cb[4], sb[4];
            #pragma unroll
            for (int k = 0; k < 4; k++) {
                cb[k] = ctw[w*36 + f0 + k];
                sb[k] = stw[w*36 + f0 + k];
            }
            #pragma unroll
            for (int k = 0; k < 4; k++) {
                re[0][k] += a0*cb[k]; im[0][k] -= a0*sb[k];
                re[1][k] += a1*cb[k]; im[1][k] -= a1*sb[k];
                re[2][k] += a2*cb[k]; im[2][k] -= a2*sb[k];
                re[3][k] += a3*cb[k]; im[3][k] -= a3*sb[k];
            }
        }
        #pragma unroll
        for (int k = 0; k < 4; k++)
            #pragma unroll
            for (int j = 0; j < 4; j++) {
                int idx = obase + (f0+k)*64 + h0 + j;
                d_xfr[idx] = re[j][k];
                d_xfi[idx] = im[j][k];
            }
    } else if (tid < 192) {
        int h = tid - 128;
        float s = 0.f;
        #pragma unroll 8
        for (int w = 0; w < 64; w += 2) s += xs[h*65 + w] - xs[h*65 + w + 1];
        d_xfr[obase + 32*64 + h] = s;
        d_xfi[obase + 32*64 + h] = 0.f;
    }
}

// ---------------- scan over L + collapsed mix/proj + pif freq-mix, fused -----
__global__ void __launch_bounds__(512) k_scanmix(const float* __restrict__ pw)
{
    __shared__ float sAr[512], sAi[512], sS[512];   // [c*16 + r] for current l
    __shared__ float ybr[32*17], ybi[32*17];        // [c*17 + hq]
    __shared__ float wsm[1024];
    __shared__ float swr[32], swi[32];
    int fi = blockIdx.x, hg = blockIdx.y;
    int tid = threadIdx.x;
    int c = tid >> 4, hq = tid & 15;
    int h = hg*16 + hq;
    for (int i = tid; i < 1024; i += 512) wsm[i] = pw[i];
    if (tid < 32) { swr[tid] = d_wr[tid]; swi[tid] = d_wi[tid]; }
    float br = d_br, bi = d_bi;
    float sr[16], si[16];
    #pragma unroll
    for (int r = 0; r < 16; r++) { sr[r] = 0.f; si[r] = 0.f; }

    for (int l = 0; l < 16; l++) {
        {
            int gidx = ((l*32 + (tid >> 4))*33 + fi)*16 + (tid & 15);
            sAr[tid] = d_Are[gidx]; sAi[tid] = d_Aim[gidx]; sS[tid] = d_S[gidx];
        }
        __syncthreads();
        int xidx = ((l*32 + c)*33 + fi)*64 + h;
        float xr = d_xfr[xidx], xi = d_xfi[xidx];
        float yr = br, yi = bi;
        const float* Ar = sAr + c*16;
        const float* Ai = sAi + c*16;
        const float* Ss = sS  + c*16;
        #pragma unroll
        for (int r = 0; r < 16; r++) {
            float ar = Ar[r], ai = Ai[r], s = Ss[r];
            float nr = ar*sr[r] - ai*si[r] + s*xr;
            float ni = ar*si[r] + ai*sr[r] + s*xi;
            sr[r] = nr; si[r] = ni;
            yr += swr[r]*nr + swr[16 + r]*ni;
            yi += swi[r]*nr + swi[16 + r]*ni;
        }
        ybr[c*17 + hq] = yr; ybi[c*17 + hq] = yi;
        __syncthreads();
        float mr = 0.f, mi = 0.f;
        const float* wrow = wsm + c*32;
        #pragma unroll
        for (int c2 = 0; c2 < 32; c2++) {
            float w = wrow[c2];
            mr += w * ybr[c2*17 + hq];
            mi += w * ybi[c2*17 + hq];
        }
        d_xfr[xidx] = mr; d_xfi[xidx] = mi;
        __syncthreads();
    }
}

// ---------------- irfft (33 -> 64) register-tiled + fused reductions ---------
__global__ void __launch_bounds__(256) k_irfft(const float* __restrict__ pif_b)
{
    __shared__ float yfr[WF*65], yfi[WF*65];   // [f][h]
    __shared__ float CwT[WF*65], SwT[WF*65];   // [f][w], scale folded
    __shared__ float ys[64*65];                // y tile for reductions
    __shared__ float rs1[8], rs2[8];
    int c = blockIdx.x, l = blockIdx.y, tid = threadIdx.x;
    for (int i = tid; i < WF*64; i += 256) {
        int f = i >> 6, w = i & 63;
        float scale = (f == 0 || f == 32) ? (1.f/64.f) : (2.f/64.f);
        float sa, ca;
        sincospif((float)((f*w) & 63) / 32.f, &sa, &ca);
        CwT[f*65 + w] = scale * ca;
        SwT[f*65 + w] = -scale * sa;
    }
    int base = ((l*32 + c)*33)*64;
    for (int i = tid; i < WF*64; i += 256) {
        int f = i >> 6, h = i & 63;
        yfr[f*65 + h] = d_xfr[base + i];
        yfi[f*65 + h] = d_xfi[base + i];
    }
    __syncthreads();
    float pb = pif_b[c];
    int hg = tid >> 4, wg = tid & 15;
    int h0 = hg*4, w0 = wg*4;
    float acc[4][4];
    #pragma unroll
    for (int j = 0; j < 4; j++)
        #pragma unroll
        for (int k = 0; k < 4; k++) acc[j][k] = pb;
    for (int f = 0; f < WF; f++) {
        float ar[4], ai[4], cb[4], sb[4];
        #pragma unroll
        for (int j = 0; j < 4; j++) {
            ar[j] = yfr[f*65 + h0 + j];
            ai[j] = yfi[f*65 + h0 + j];
        }
        #pragma unroll
        for (int k = 0; k < 4; k++) {
            cb[k] = CwT[f*65 + w0 + k];
            sb[k] = SwT[f*65 + w0 + k];
        }
        #pragma unroll
        for (int j = 0; j < 4; j++)
            #pragma unroll
            for (int k = 0; k < 4; k++)
                acc[j][k] += ar[j]*cb[k] + ai[j]*sb[k];
    }
    float s = 0.f, s2 = 0.f;
    int ob = (l*32 + c)*4096;
    #pragma unroll
    for (int j = 0; j < 4; j++)
        #pragma unroll
        for (int k = 0; k < 4; k++) {
            float v = acc[j][k];
            ys[(h0+j)*65 + w0 + k] = v;
            d_y2[ob + (h0+j)*64 + w0 + k] = v;
            s += v; s2 += v*v;
        }
    int warp = tid >> 5, lane = tid & 31;
    #pragma unroll
    for (int off = 16; off > 0; off >>= 1) {
        s  += __shfl_down_sync(0xffffffffu, s,  off);
        s2 += __shfl_down_sync(0xffffffffu, s2, off);
    }
    if (lane == 0) { rs1[warp] = s; rs2[warp] = s2; }
    __syncthreads();
    if (tid == 0) {
        float t1 = 0.f, t2 = 0.f;
        #pragma unroll
        for (int q = 0; q < 8; q++) { t1 += rs1[q]; t2 += rs2[q]; }
        d_psum[l*32 + c] = t1;
        d_psq [l*32 + c] = t2;
    }
    if (tid < 64) {
        float rsum = 0.f;
        #pragma unroll 8
        for (int w = 0; w < 64; w++) rsum += ys[tid*65 + w];
        d_ymean[(l*32 + c)*64 + tid] = rsum / 64.f;
    }
}

// ---------------- group stats + gate MLP per (l,h) ---------------------------
__global__ void k_gatemlp(const float* __restrict__ gn_w, const float* __restrict__ gn_b,
                          const float* __restrict__ g1w, const float* __restrict__ g1b,
                          const float* __restrict__ g2w, const float* __restrict__ g2b)
{
    __shared__ float smu[4], srstd[4];
    int l = blockIdx.x, h = threadIdx.x;
    if (h < 4) {
        float s = 0.f, s2 = 0.f;
        #pragma unroll
        for (int c8 = 0; c8 < 8; c8++) {
            s  += d_psum[l*32 + h*8 + c8];
            s2 += d_psq [l*32 + h*8 + c8];
        }
        float mu  = s / 32768.f;
        float var = s2 / 32768.f - mu*mu;
        float rst = rsqrtf(var + 1e-5f);
        smu[h] = mu; srstd[h] = rst;
        d_mu[l*4 + h] = mu; d_rstd[l*4 + h] = rst;
    }
    __syncthreads();
    float hid[4];
    #pragma unroll
    for (int m = 0; m < 4; m++) hid[m] = g1b[m];
    #pragma unroll
    for (int c = 0; c < 32; c++) {
        int g = c >> 3;
        float ym = (d_ymean[(l*32 + c)*64 + h] - smu[g]) * srstd[g] * gn_w[c] + gn_b[c];
        #pragma unroll
        for (int m = 0; m < 4; m++) hid[m] += g1w[m*32 + c] * ym;
    }
    #pragma unroll
    for (int m = 0; m < 4; m++) hid[m] = fsilu(hid[m]);
    #pragma unroll
    for (int c = 0; c < 32; c++) {
        float a = g2b[c];
        #pragma unroll
        for (int m = 0; m < 4; m++) a += g2w[c*4 + m] * hid[m];
        d_gate[(l*32 + c)*64 + h] = fsigmoid(a);
    }
}

// ---------------- final: normalize + gate + residual -------------------------
__global__ void k_out(const float* __restrict__ x, const float* __restrict__ gn_w,
                      const float* __restrict__ gn_b, float* __restrict__ out)
{
    int i = blockIdx.x * 256 + threadIdx.x;
    int w = i & 63;
    int h = (i >> 6) & 63;
    int l = (i >> 12) & 15;
    int c = i >> 16;
    int yidx = (l*32 + c)*4096 + h*64 + w;
    int g = c >> 3;
    float z = (d_y2[yidx] - d_mu[l*4 + g]) * d_rstd[l*4 + g] * gn_w[c] + gn_b[c];
    out[i] = x[i] + z * d_gate[(l*32 + c)*64 + h];
}

// ---------------- launch -----------------------------------------------------
extern "C" void kernel_launch(void* const* d_in, const int* in_sizes, int n_in,
                              void* d_out, int out_size)
{
    const float* x       = (const float*)d_in[0];
    const float* dt      = (const float*)d_in[1];
    const float* conv1_w = (const float*)d_in[2];
    const float* conv1_b = (const float*)d_in[3];
    const float* conv2_w = (const float*)d_in[4];
    const float* conv2_b = (const float*)d_in[5];
    const float* gfc_w   = (const float*)d_in[6];
    const float* gfc_b   = (const float*)d_in[7];
    const float* head_w  = (const float*)d_in[8];
    const float* head_b  = (const float*)d_in[9];
    const float* mix_w   = (const float*)d_in[10];
    const float* mix_b   = (const float*)d_in[11];
    const float* rank_s  = (const float*)d_in[12];
    const float* proj_w  = (const float*)d_in[13];
    const float* proj_b  = (const float*)d_in[14];
    const float* pif_w   = (const float*)d_in[15];
    const float* pif_b   = (const float*)d_in[16];
    const float* gn_w    = (const float*)d_in[17];
    const float* gn_b    = (const float*)d_in[18];
    const float* g1_w    = (const float*)d_in[19];
    const float* g1_b    = (const float*)d_in[20];
    const float* g2_w    = (const float*)d_in[21];
    const float* g2_b    = (const float*)d_in[22];
    float* out = (float*)d_out;

    // allow >48KB dynamic smem for the tensor-core convs (idempotent host call)
    cudaFuncSetAttribute(k_conv1, cudaFuncAttributeMaxDynamicSharedMemorySize, CONV_SMEM_BYTES);
    cudaFuncSetAttribute(k_conv2, cudaFuncAttributeMaxDynamicSharedMemorySize, CONV_SMEM_BYTES);

    // Launch order keeps the kernel-of-interest in slot 4 (ncu captures launch #4):
    // this round that's the new tensor-core k_conv1.
    k_rfft<<<dim3(32, 16), 256>>>(x);
    k_prep<<<1, 32>>>(mix_w, mix_b, rank_s, proj_w, proj_b);
    k_prep<<<1, 32>>>(mix_w, mix_b, rank_s, proj_w, proj_b);
    k_conv1<<<dim3(32, 16), 256, CONV_SMEM_BYTES>>>(x, conv1_w, conv1_b);
    k_conv2<<<dim3(32, 16), 256, CONV_SMEM_BYTES>>>(conv2_w, conv2_b);
    k_sum<<<512, 256>>>();
    k_headall<<<dim3(3, 16), 512>>>(gfc_w, gfc_b, head_w, head_b, dt);
    k_scanmix<<<dim3(33, 4), 512>>>(pif_w);
    k_irfft<<<dim3(32, 16), 256>>>(pif_b);
    k_gatemlp<<<16, 64>>>(gn_w, gn_b, g1_w, g1_b, g2_w, g2_b);
    k_out<<<8192, 256>>>(x, gn_w, gn_b, out);
}

// round 8
// speedup vs baseline: 1.3377x; 1.3377x over previous
#include <cuda_runtime.h>
#include <math.h>

#define LL 16
#define CC 32
#define HH 64
#define WW 64
#define WF 33
#define RR 16

// ---------------- scratch (device globals; no allocs allowed) ----------------
__device__ float d_f1[LL*CC*HH*WW];     // conv1 out (l,c,h,w)
__device__ float d_cs[LL*CC*WW];        // per (l,c) column sums over h of conv2 out
__device__ float d_Are[LL*CC*WF*RR];
__device__ float d_Aim[LL*CC*WF*RR];
__device__ float d_S  [LL*CC*WF*RR];
__device__ float d_xfr[LL*CC*WF*HH];    // rfft(x); overwritten in-place by scanmix
__device__ float d_xfi[LL*CC*WF*HH];
__device__ float d_y2 [LL*CC*HH*WW];    // pif-mixed spatial output
__device__ float d_psum[LL*CC];
__device__ float d_psq [LL*CC];
__device__ float d_ymean[LL*CC*HH];     // raw mean over w of y2
__device__ float d_wr[CC];
__device__ float d_wi[CC];
__device__ float d_br;
__device__ float d_bi;

__device__ __forceinline__ float fsigmoid(float x) {
    return 1.f / (1.f + __expf(-x));
}
__device__ __forceinline__ float fsilu(float x) {
    return x / (1.f + __expf(-x));
}

// ---------------- conv 3x3 SAME + silu, 32->32 ch (R5 measured-best shape) ---
// grid (16 htiles of 4 rows, 16 l), block 256 (64 w x 4 channel-groups of 8).
// MODE 0: store silu output to d_f1. MODE 1: column-sum 4 rows + atomicAdd d_cs.
template <int MODE>
__device__ __forceinline__ void conv_body(const float* __restrict__ in, int in_base,
                                          int cstride,
                                          const float* __restrict__ wgt,
                                          const float* __restrict__ bias,
                                          float* __restrict__ out)
{
    __shared__ float wsm[32*32*9];     // [ci][co][9]
    __shared__ float tile[2][6*66];    // rows h0-1..h0+4, cols -1..64
    int l  = blockIdx.y;
    int h0 = blockIdx.x * 4;
    int tid = threadIdx.x;
    int tx = tid & 63;                 // w
    int cg = tid >> 6;                 // 0..3 (out-channel group of 8)

    if (MODE == 0) {
        // zero d_cs for conv2's atomic accumulation (256 blocks x 128 = 32768)
        int blin = blockIdx.y * 16 + blockIdx.x;
        if (tid < 128) d_cs[blin * 128 + tid] = 0.f;
    }

    for (int i = tid; i < 32*32*9; i += 256) {
        int j = i % 9; int p = i / 9; int co = p & 31; int ci = p >> 5;
        wsm[(ci*32 + co)*9 + j] = wgt[co*288 + ci*9 + j];
    }
    const float* inb = in + in_base;
    for (int i = tid; i < 6*66; i += 256) {
        int r = i / 66, cc = i % 66;
        int gh = h0 - 1 + r, gw = cc - 1;
        tile[0][i] = (gh >= 0 && gh < 64 && gw >= 0 && gw < 64) ? inb[gh*64 + gw] : 0.f;
    }
    __syncthreads();

    float acc[4][8];
    #pragma unroll
    for (int a = 0; a < 4; a++)
        #pragma unroll
        for (int o = 0; o < 8; o++) acc[a][o] = 0.f;

    for (int ci = 0; ci < 32; ci++) {
        int cur = ci & 1;
        if (ci + 1 < 32) {                           // prefetch next channel tile
            const float* src = inb + (ci + 1) * cstride;
            for (int i = tid; i < 6*66; i += 256) {
                int r = i / 66, cc = i % 66;
                int gh = h0 - 1 + r, gw = cc - 1;
                tile[cur ^ 1][i] = (gh >= 0 && gh < 64 && gw >= 0 && gw < 64)
                                   ? src[gh*64 + gw] : 0.f;
            }
        }
        float v[6][3];
        #pragma unroll
        for (int dy = 0; dy < 6; dy++)
            #pragma unroll
            for (int dx = 0; dx < 3; dx++)
                v[dy][dx] = tile[cur][dy*66 + tx + dx];
        const float* wp = &wsm[(ci*32 + cg*8)*9];
        #pragma unroll
        for (int o = 0; o < 8; o++) {
            float w0 = wp[o*9+0], w1 = wp[o*9+1], w2 = wp[o*9+2];
            float w3 = wp[o*9+3], w4 = wp[o*9+4], w5 = wp[o*9+5];
            float w6 = wp[o*9+6], w7 = wp[o*9+7], w8 = wp[o*9+8];
            #pragma unroll
            for (int a = 0; a < 4; a++) {
                acc[a][o] += v[a  ][0]*w0 + v[a  ][1]*w1 + v[a  ][2]*w2
                           + v[a+1][0]*w3 + v[a+1][1]*w4 + v[a+1][2]*w5
                           + v[a+2][0]*w6 + v[a+2][1]*w7 + v[a+2][2]*w8;
            }
        }
        __syncthreads();
    }
    if (MODE == 0) {
        #pragma unroll
        for (int a = 0; a < 4; a++) {
            int h = h0 + a;
            #pragma unroll
            for (int o = 0; o < 8; o++) {
                int co = cg*8 + o;
                float xv = acc[a][o] + bias[co];
                out[((l*32 + co)*64 + h)*64 + tx] = fsilu(xv);
            }
        }
    } else {
        #pragma unroll
        for (int o = 0; o < 8; o++) {
            int co = cg*8 + o;
            float b = bias[co];
            float csum = 0.f;
            #pragma unroll
            for (int a = 0; a < 4; a++) csum += fsilu(acc[a][o] + b);
            atomicAdd(&d_cs[(l*32 + co)*64 + tx], csum);
        }
    }
}

__global__ void __launch_bounds__(256)
k_conv1(const float* __restrict__ x, const float* __restrict__ w,
        const float* __restrict__ b)
{
    conv_body<0>(x, blockIdx.y * 4096, 16*4096, w, b, d_f1);   // x layout (c,l,h,w)
}
__global__ void __launch_bounds__(256)
k_conv2(const float* __restrict__ w, const float* __restrict__ b)
{
    conv_body<1>(d_f1, blockIdx.y * 32 * 4096, 4096, w, b, (float*)0);  // (l,c,h,w)
}

// ---------------- rfft over W (64 -> 33 bins), register-tiled + prep folded --
// grid (33, 16): blockIdx.x<32 = DFT tile for channel c; block (32,0) does prep.
__global__ void __launch_bounds__(256)
k_rfft(const float* __restrict__ x,
       const float* __restrict__ mix_w, const float* __restrict__ mix_b,
       const float* __restrict__ rs, const float* __restrict__ pw,
       const float* __restrict__ pb)
{
    int c = blockIdx.x, l = blockIdx.y, tid = threadIdx.x;
    if (c == 32) {
        // prep: collapse mix/rank_scale/proj into 64-weight dot
        if (l == 0 && tid < 32) {
            int j = tid;
            float swr = 0.f, swi = 0.f;
            for (int r = 0; r < RR; r++) {
                float a = rs[r] * pw[r];
                swr += a * mix_w[r*32 + j];
                swi += a * mix_w[(16+r)*32 + j];
            }
            d_wr[j] = swr; d_wi[j] = swi;
            if (j == 0) {
                float br = pb[0], bi = 0.f;
                for (int r = 0; r < RR; r++) {
                    float a = rs[r] * pw[r];
                    br += a * mix_b[r];
                    bi += a * mix_b[16+r];
                }
                d_br = br; d_bi = bi;
            }
        }
        return;
    }
    __shared__ float xs[64*65];
    __shared__ float ct[64], st[64];
    __shared__ float ctw[64*36], stw[64*36];  // [w][f0..32]
    const float* p = x + (size_t)(c*16 + l)*4096;
    for (int i = tid; i < 4096; i += 256) xs[(i >> 6)*65 + (i & 63)] = p[i];
    if (tid < 64) sincospif(tid / 32.f, &st[tid], &ct[tid]);
    __syncthreads();
    for (int i = tid; i < 64*33; i += 256) {
        int w = i / 33, f = i % 33;
        int k = (w*f) & 63;
        ctw[w*36 + f] = ct[k]; stw[w*36 + f] = st[k];
    }
    __syncthreads();
    int obase = ((l*32 + c)*33)*64;
    if (tid < 128) {
        int hg = tid >> 3, fg = tid & 7;
        int h0 = hg*4, f0 = fg*4;
        float re[4][4], im[4][4];
        #pragma unroll
        for (int j = 0; j < 4; j++)
            #pragma unroll
            for (int k = 0; k < 4; k++) { re[j][k] = 0.f; im[j][k] = 0.f; }
        for (int w = 0; w < 64; w++) {
            float a0 = xs[(h0+0)*65 + w];
            float a1 = xs[(h0+1)*65 + w];
            float a2 = xs[(h0+2)*65 + w];
            float a3 = xs[(h0+3)*65 + w];
            float cb[4], sb[4];
            #pragma unroll
            for (int k = 0; k < 4; k++) {
                cb[k] = ctw[w*36 + f0 + k];
                sb[k] = stw[w*36 + f0 + k];
            }
            #pragma unroll
            for (int k = 0; k < 4; k++) {
                re[0][k] += a0*cb[k]; im[0][k] -= a0*sb[k];
                re[1][k] += a1*cb[k]; im[1][k] -= a1*sb[k];
                re[2][k] += a2*cb[k]; im[2][k] -= a2*sb[k];
                re[3][k] += a3*cb[k]; im[3][k] -= a3*sb[k];
            }
        }
        #pragma unroll
        for (int k = 0; k < 4; k++)
            #pragma unroll
            for (int j = 0; j < 4; j++) {
                int idx = obase + (f0+k)*64 + h0 + j;
                d_xfr[idx] = re[j][k];
                d_xfi[idx] = im[j][k];
            }
    } else if (tid < 192) {
        int h = tid - 128;
        float s = 0.f;
        #pragma unroll 8
        for (int w = 0; w < 64; w += 2) s += xs[h*65 + w] - xs[h*65 + w + 1];
        d_xfr[obase + 32*64 + h] = s;
        d_xfi[obase + 32*64 + h] = 0.f;
    }
}

// ---------------- glob + adaptive pool + head (cmean from d_cs inline) -------
// grid (3 f-chunks of 11, 16 l), block 512 (thread = (c,r))
__global__ void k_headall(const float* __restrict__ gfc_w, const float* __restrict__ gfc_b,
                          const float* __restrict__ head_w, const float* __restrict__ head_b,
                          const float* __restrict__ dt)
{
    __shared__ float gl[32];
    __shared__ float fl[32];
    __shared__ float cm[32];
    int f0 = blockIdx.x * 11, l = blockIdx.y, tid = threadIdx.x;
    if (tid < 32) {
        float s = 0.f;
        const float* csp = d_cs + (l*32 + tid)*64;
        #pragma unroll 8
        for (int w = 0; w < 64; w++) s += csp[w];
        cm[tid] = s / 4096.f;
    }
    __syncthreads();
    if (tid < 32) {
        float a = gfc_b[tid];
        #pragma unroll
        for (int ci = 0; ci < 32; ci++) a += cm[ci] * gfc_w[tid*32 + ci];
        gl[tid] = fsigmoid(a);
    }
    float dtl = dt[l];
    int c = tid >> 4, r = tid & 15;
    int k0 = (c*16 + r)*3;
    for (int ff = 0; ff < 11; ff++) {
        int fi = f0 + ff;
        __syncthreads();
        if (tid < 32) {
            int st = (fi*64) / 33;
            int en = ((fi+1)*64 + 32) / 33;
            float s = 0.f;
            for (int k = st; k < en; k++) s += d_cs[(l*32 + tid)*64 + k];
            fl[tid] = gl[tid] * s / (64.f * (float)(en - st));
        }
        __syncthreads();
        float p[3];
        #pragma unroll
        for (int t = 0; t < 3; t++) {
            const float* wrow = head_w + (k0 + t)*32;
            float a = head_b[k0 + t];
            #pragma unroll
            for (int ci = 0; ci < 32; ci++) a += fl[ci] * wrow[ci];
            p[t] = a;
        }
        float nu = (p[0] > 20.f) ? p[0] : log1pf(__expf(p[0]));
        float decay = __expf(-nu * dtl);
        float ang = tanhf(p[1]) * 3.14159265358979323846f * dtl;
        float sa, ca;
        __sincosf(ang, &sa, &ca);
        float sg = fsigmoid(p[2]);
        float g  = 1.f - __expf(-2.f * dtl);
        int idx = ((l*32 + c)*33 + fi)*16 + r;
        d_Are[idx] = decay * ca;
        d_Aim[idx] = decay * sa;
        d_S[idx]   = sg * g;
    }
}

// ---------------- scan over L + collapsed mix/proj + pif freq-mix, fused -----
// grid (33 fi, 4 h-groups of 16), block 512 (thread = c*16 + hq).
__global__ void __launch_bounds__(512) k_scanmix(const float* __restrict__ pw)
{
    __shared__ float sAr[512], sAi[512], sS[512];   // [c*16 + r] for current l
    __shared__ float ybr[32*17], ybi[32*17];        // [c*17 + hq]
    __shared__ float wsm[1024];
    __shared__ float swr[32], swi[32];
    int fi = blockIdx.x, hg = blockIdx.y;
    int tid = threadIdx.x;
    int c = tid >> 4, hq = tid & 15;
    int h = hg*16 + hq;
    for (int i = tid; i < 1024; i += 512) wsm[i] = pw[i];
    if (tid < 32) { swr[tid] = d_wr[tid]; swi[tid] = d_wi[tid]; }
    float br = d_br, bi = d_bi;
    float sr[16], si[16];
    #pragma unroll
    for (int r = 0; r < 16; r++) { sr[r] = 0.f; si[r] = 0.f; }

    for (int l = 0; l < 16; l++) {
        {
            int gidx = ((l*32 + (tid >> 4))*33 + fi)*16 + (tid & 15);
            sAr[tid] = d_Are[gidx]; sAi[tid] = d_Aim[gidx]; sS[tid] = d_S[gidx];
        }
        __syncthreads();
        int xidx = ((l*32 + c)*33 + fi)*64 + h;
        float xr = d_xfr[xidx], xi = d_xfi[xidx];
        float yr = br, yi = bi;
        const float* Ar = sAr + c*16;
        const float* Ai = sAi + c*16;
        const float* Ss = sS  + c*16;
        #pragma unroll
        for (int r = 0; r < 16; r++) {
            float ar = Ar[r], ai = Ai[r], s = Ss[r];
            float nr = ar*sr[r] - ai*si[r] + s*xr;
            float ni = ar*si[r] + ai*sr[r] + s*xi;
            sr[r] = nr; si[r] = ni;
            yr += swr[r]*nr + swr[16 + r]*ni;
            yi += swi[r]*nr + swi[16 + r]*ni;
        }
        ybr[c*17 + hq] = yr; ybi[c*17 + hq] = yi;
        __syncthreads();
        float mr = 0.f, mi = 0.f;
        const float* wrow = wsm + c*32;
        #pragma unroll
        for (int c2 = 0; c2 < 32; c2++) {
            float w = wrow[c2];
            mr += w * ybr[c2*17 + hq];
            mi += w * ybi[c2*17 + hq];
        }
        d_xfr[xidx] = mr; d_xfi[xidx] = mi;
        __syncthreads();
    }
}

// ---------------- irfft (33 -> 64) register-tiled + fused reductions ---------
// grid (32 o, 16 l), block 256 = 16 hg x 16 wg, thread 4h x 4w.
__global__ void __launch_bounds__(256) k_irfft(const float* __restrict__ pif_b)
{
    __shared__ float yfr[WF*65], yfi[WF*65];   // [f][h]
    __shared__ float CwT[WF*65], SwT[WF*65];   // [f][w], scale folded
    __shared__ float ys[64*65];                // y tile for reductions
    __shared__ float ct[64], st[64];
    __shared__ float rs1[8], rs2[8];
    int c = blockIdx.x, l = blockIdx.y, tid = threadIdx.x;
    int base = ((l*32 + c)*33)*64;
    for (int i = tid; i < WF*64; i += 256) {
        int f = i >> 6, h = i & 63;
        yfr[f*65 + h] = d_xfr[base + i];
        yfi[f*65 + h] = d_xfi[base + i];
    }
    if (tid < 64) sincospif(tid / 32.f, &st[tid], &ct[tid]);
    __syncthreads();
    for (int i = tid; i < WF*64; i += 256) {
        int f = i >> 6, w = i & 63;
        float scale = (f == 0 || f == 32) ? (1.f/64.f) : (2.f/64.f);
        int k = (f*w) & 63;
        CwT[f*65 + w] = scale * ct[k];
        SwT[f*65 + w] = -scale * st[k];
    }
    __syncthreads();
    float pb = pif_b[c];
    int hg = tid >> 4, wg = tid & 15;
    int h0 = hg*4, w0 = wg*4;
    float acc[4][4];
    #pragma unroll
    for (int j = 0; j < 4; j++)
        #pragma unroll
        for (int k = 0; k < 4; k++) acc[j][k] = pb;
    for (int f = 0; f < WF; f++) {
        float ar[4], ai[4], cb[4], sb[4];
        #pragma unroll
        for (int j = 0; j < 4; j++) {
            ar[j] = yfr[f*65 + h0 + j];
            ai[j] = yfi[f*65 + h0 + j];
        }
        #pragma unroll
        for (int k = 0; k < 4; k++) {
            cb[k] = CwT[f*65 + w0 + k];
            sb[k] = SwT[f*65 + w0 + k];
        }
        #pragma unroll
        for (int j = 0; j < 4; j++)
            #pragma unroll
            for (int k = 0; k < 4; k++)
                acc[j][k] += ar[j]*cb[k] + ai[j]*sb[k];
    }
    float s = 0.f, s2 = 0.f;
    int ob = (l*32 + c)*4096;
    #pragma unroll
    for (int j = 0; j < 4; j++)
        #pragma unroll
        for (int k = 0; k < 4; k++) {
            float v = acc[j][k];
            ys[(h0+j)*65 + w0 + k] = v;
            d_y2[ob + (h0+j)*64 + w0 + k] = v;
            s += v; s2 += v*v;
        }
    int warp = tid >> 5, lane = tid & 31;
    #pragma unroll
    for (int off = 16; off > 0; off >>= 1) {
        s  += __shfl_down_sync(0xffffffffu, s,  off);
        s2 += __shfl_down_sync(0xffffffffu, s2, off);
    }
    if (lane == 0) { rs1[warp] = s; rs2[warp] = s2; }
    __syncthreads();
    if (tid == 0) {
        float t1 = 0.f, t2 = 0.f;
        #pragma unroll
        for (int q = 0; q < 8; q++) { t1 += rs1[q]; t2 += rs2[q]; }
        d_psum[l*32 + c] = t1;
        d_psq [l*32 + c] = t2;
    }
    if (tid < 64) {
        float rsum = 0.f;
        #pragma unroll 8
        for (int w = 0; w < 64; w++) rsum += ys[tid*65 + w];
        d_ymean[(l*32 + c)*64 + tid] = rsum / 64.f;
    }
}

// ---------------- fused groupnorm stats + gate MLP + output ------------------
// grid (16 htiles of 4, 16 l), block 256 (4 h' x 64 w).
__global__ void __launch_bounds__(256)
k_outgate(const float* __restrict__ x,
          const float* __restrict__ gn_w, const float* __restrict__ gn_b,
          const float* __restrict__ g1w, const float* __restrict__ g1b,
          const float* __restrict__ g2w, const float* __restrict__ g2b,
          float* __restrict__ out)
{
    __shared__ float smu[4], srstd[4];
    __shared__ float sym[4][32];
    __shared__ float shid[4][4];
    __shared__ float sgate[4][33];
    int h0 = blockIdx.x * 4, l = blockIdx.y;
    int tid = threadIdx.x;
    if (tid < 4) {
        float s = 0.f, s2 = 0.f;
        #pragma unroll
        for (int c8 = 0; c8 < 8; c8++) {
            s  += d_psum[l*32 + tid*8 + c8];
            s2 += d_psq [l*32 + tid*8 + c8];
        }
        float mu  = s / 32768.f;
        float var = s2 / 32768.f - mu*mu;
        smu[tid] = mu; srstd[tid] = rsqrtf(var + 1e-5f);
    }
    __syncthreads();
    if (tid < 128) {
        int hp = tid >> 5, c = tid & 31;
        int g = c >> 3;
        sym[hp][c] = (d_ymean[(l*32 + c)*64 + h0 + hp] - smu[g]) * srstd[g]
                     * gn_w[c] + gn_b[c];
    }
    __syncthreads();
    if (tid < 16) {
        int hp = tid >> 2, m = tid & 3;
        float a = g1b[m];
        #pragma unroll
        for (int c = 0; c < 32; c++) a += g1w[m*32 + c] * sym[hp][c];
        shid[hp][m] = fsilu(a);
    }
    __syncthreads();
    if (tid < 128) {
        int hp = tid >> 5, c = tid & 31;
        float a = g2b[c];
        #pragma unroll
        for (int m = 0; m < 4; m++) a += g2w[c*4 + m] * shid[hp][m];
        sgate[hp][c] = fsigmoid(a);
    }
    __syncthreads();
    int hp = tid >> 6, w = tid & 63;
    int h = h0 + hp;
    #pragma unroll 4
    for (int c = 0; c < 32; c++) {
        int g = c >> 3;
        float z = (d_y2[((l*32 + c)*64 + h)*64 + w] - smu[g]) * srstd[g]
                  * gn_w[c] + gn_b[c];
        int oidx = ((c*16 + l)*64 + h)*64 + w;
        out[oidx] = x[oidx] + z * sgate[hp][c];
    }
}

// ---------------- launch -----------------------------------------------------
extern "C" void kernel_launch(void* const* d_in, const int* in_sizes, int n_in,
                              void* d_out, int out_size)
{
    const float* x       = (const float*)d_in[0];
    const float* dt      = (const float*)d_in[1];
    const float* conv1_w = (const float*)d_in[2];
    const float* conv1_b = (const float*)d_in[3];
    const float* conv2_w = (const float*)d_in[4];
    const float* conv2_b = (const float*)d_in[5];
    const float* gfc_w   = (const float*)d_in[6];
    const float* gfc_b   = (const float*)d_in[7];
    const float* head_w  = (const float*)d_in[8];
    const float* head_b  = (const float*)d_in[9];
    const float* mix_w   = (const float*)d_in[10];
    const float* mix_b   = (const float*)d_in[11];
    const float* rank_s  = (const float*)d_in[12];
    const float* proj_w  = (const float*)d_in[13];
    const float* proj_b  = (const float*)d_in[14];
    const float* pif_w   = (const float*)d_in[15];
    const float* pif_b   = (const float*)d_in[16];
    const float* gn_w    = (const float*)d_in[17];
    const float* gn_b    = (const float*)d_in[18];
    const float* g1_w    = (const float*)d_in[19];
    const float* g1_b    = (const float*)d_in[20];
    const float* g2_w    = (const float*)d_in[21];
    const float* g2_b    = (const float*)d_in[22];
    float* out = (float*)d_out;

    // 7 launches. Slot 4 (ncu capture) = k_headall this round.
    k_rfft<<<dim3(33, 16), 256>>>(x, mix_w, mix_b, rank_s, proj_w, proj_b);
    k_conv1<<<dim3(16, 16), 256>>>(x, conv1_w, conv1_b);
    k_conv2<<<dim3(16, 16), 256>>>(conv2_w, conv2_b);
    k_headall<<<dim3(3, 16), 512>>>(gfc_w, gfc_b, head_w, head_b, dt);
    k_scanmix<<<dim3(33, 4), 512>>>(pif_w);
    k_irfft<<<dim3(32, 16), 256>>>(pif_b);
    k_outgate<<<dim3(16, 16), 256>>>(x, gn_w, gn_b, g1_w, g1_b, g2_w, g2_b, out);
}

// round 9
// speedup vs baseline: 3.0852x; 2.3062x over previous
#include <cuda_runtime.h>
#include <math.h>

#define LL 16
#define CC 32
#define HH 64
#define WW 64
#define WF 33
#define RR 16

// ---------------- scratch (device globals; no allocs allowed) ----------------
__device__ float d_f1[LL*CC*HH*WW];     // conv1 out (l,c,h,w)
__device__ float d_cs[LL*CC*WW];        // per (l,c) column sums over h of conv2 out
__device__ float d_hwT[32*1536];        // head_w transposed: [ci][row]
__device__ float d_Are[LL*CC*WF*RR];
__device__ float d_Aim[LL*CC*WF*RR];
__device__ float d_S  [LL*CC*WF*RR];
__device__ float d_xfr[LL*CC*WF*HH];    // rfft(x); overwritten in-place by scanmix
__device__ float d_xfi[LL*CC*WF*HH];
__device__ float d_y2 [LL*CC*HH*WW];    // pif-mixed spatial output
__device__ float d_psum[LL*CC];
__device__ float d_psq [LL*CC];
__device__ float d_ymean[LL*CC*HH];     // raw mean over w of y2
__device__ float d_wr[CC];
__device__ float d_wi[CC];
__device__ float d_br;
__device__ float d_bi;

__device__ __forceinline__ float fsigmoid(float x) {
    return 1.f / (1.f + __expf(-x));
}
__device__ __forceinline__ float fsilu(float x) {
    return x / (1.f + __expf(-x));
}

// ---------------- conv 3x3 SAME + silu, 32->32 ch (R5 measured-best shape) ---
// grid (16 htiles of 4 rows, 16 l), block 256 (64 w x 4 channel-groups of 8).
// MODE 0: store silu output to d_f1. MODE 1: column-sum 4 rows + atomicAdd d_cs.
template <int MODE>
__device__ __forceinline__ void conv_body(const float* __restrict__ in, int in_base,
                                          int cstride,
                                          const float* __restrict__ wgt,
                                          const float* __restrict__ bias,
                                          float* __restrict__ out)
{
    __shared__ float wsm[32*32*9];     // [ci][co][9]
    __shared__ float tile[2][6*66];    // rows h0-1..h0+4, cols -1..64
    int l  = blockIdx.y;
    int h0 = blockIdx.x * 4;
    int tid = threadIdx.x;
    int tx = tid & 63;                 // w
    int cg = tid >> 6;                 // 0..3 (out-channel group of 8)

    if (MODE == 0) {
        // zero d_cs for conv2's atomic accumulation (256 blocks x 128 = 32768)
        int blin = blockIdx.y * 16 + blockIdx.x;
        if (tid < 128) d_cs[blin * 128 + tid] = 0.f;
    }

    for (int i = tid; i < 32*32*9; i += 256) {
        int j = i % 9; int p = i / 9; int co = p & 31; int ci = p >> 5;
        wsm[(ci*32 + co)*9 + j] = wgt[co*288 + ci*9 + j];
    }
    const float* inb = in + in_base;
    for (int i = tid; i < 6*66; i += 256) {
        int r = i / 66, cc = i % 66;
        int gh = h0 - 1 + r, gw = cc - 1;
        tile[0][i] = (gh >= 0 && gh < 64 && gw >= 0 && gw < 64) ? inb[gh*64 + gw] : 0.f;
    }
    __syncthreads();

    float acc[4][8];
    #pragma unroll
    for (int a = 0; a < 4; a++)
        #pragma unroll
        for (int o = 0; o < 8; o++) acc[a][o] = 0.f;

    for (int ci = 0; ci < 32; ci++) {
        int cur = ci & 1;
        if (ci + 1 < 32) {                           // prefetch next channel tile
            const float* src = inb + (ci + 1) * cstride;
            for (int i = tid; i < 6*66; i += 256) {
                int r = i / 66, cc = i % 66;
                int gh = h0 - 1 + r, gw = cc - 1;
                tile[cur ^ 1][i] = (gh >= 0 && gh < 64 && gw >= 0 && gw < 64)
                                   ? src[gh*64 + gw] : 0.f;
            }
        }
        float v[6][3];
        #pragma unroll
        for (int dy = 0; dy < 6; dy++)
            #pragma unroll
            for (int dx = 0; dx < 3; dx++)
                v[dy][dx] = tile[cur][dy*66 + tx + dx];
        const float* wp = &wsm[(ci*32 + cg*8)*9];
        #pragma unroll
        for (int o = 0; o < 8; o++) {
            float w0 = wp[o*9+0], w1 = wp[o*9+1], w2 = wp[o*9+2];
            float w3 = wp[o*9+3], w4 = wp[o*9+4], w5 = wp[o*9+5];
            float w6 = wp[o*9+6], w7 = wp[o*9+7], w8 = wp[o*9+8];
            #pragma unroll
            for (int a = 0; a < 4; a++) {
                acc[a][o] += v[a  ][0]*w0 + v[a  ][1]*w1 + v[a  ][2]*w2
                           + v[a+1][0]*w3 + v[a+1][1]*w4 + v[a+1][2]*w5
                           + v[a+2][0]*w6 + v[a+2][1]*w7 + v[a+2][2]*w8;
            }
        }
        __syncthreads();
    }
    if (MODE == 0) {
        #pragma unroll
        for (int a = 0; a < 4; a++) {
            int h = h0 + a;
            #pragma unroll
            for (int o = 0; o < 8; o++) {
                int co = cg*8 + o;
                float xv = acc[a][o] + bias[co];
                out[((l*32 + co)*64 + h)*64 + tx] = fsilu(xv);
            }
        }
    } else {
        #pragma unroll
        for (int o = 0; o < 8; o++) {
            int co = cg*8 + o;
            float b = bias[co];
            float csum = 0.f;
            #pragma unroll
            for (int a = 0; a < 4; a++) csum += fsilu(acc[a][o] + b);
            atomicAdd(&d_cs[(l*32 + co)*64 + tx], csum);
        }
    }
}

__global__ void __launch_bounds__(256)
k_conv1(const float* __restrict__ x, const float* __restrict__ w,
        const float* __restrict__ b)
{
    conv_body<0>(x, blockIdx.y * 4096, 16*4096, w, b, d_f1);   // x layout (c,l,h,w)
}
__global__ void __launch_bounds__(256)
k_conv2(const float* __restrict__ w, const float* __restrict__ b)
{
    conv_body<1>(d_f1, blockIdx.y * 32 * 4096, 4096, w, b, (float*)0);  // (l,c,h,w)
}

// ---------------- rfft over W (64 -> 33 bins) + prep + head_w transpose ------
// grid (33, 16): blockIdx.x<32 = DFT tile for channel c; blocks (32, l) do
// prep (l==0) and the head_w transpose (all l, 1/16 each).
__global__ void __launch_bounds__(256)
k_rfft(const float* __restrict__ x,
       const float* __restrict__ mix_w, const float* __restrict__ mix_b,
       const float* __restrict__ rs, const float* __restrict__ pw,
       const float* __restrict__ pb, const float* __restrict__ head_w)
{
    int c = blockIdx.x, l = blockIdx.y, tid = threadIdx.x;
    if (c == 32) {
        // transpose head_w[row*32+ci] -> d_hwT[ci*1536+row]; 3072 elems/block
        int i0 = l * 3072;
        for (int i = i0 + tid; i < i0 + 3072; i += 256) {
            int row = i >> 5, ci = i & 31;
            d_hwT[ci*1536 + row] = head_w[i];
        }
        // prep: collapse mix/rank_scale/proj into 64-weight dot
        if (l == 0 && tid < 32) {
            int j = tid;
            float swr = 0.f, swi = 0.f;
            for (int r = 0; r < RR; r++) {
                float a = rs[r] * pw[r];
                swr += a * mix_w[r*32 + j];
                swi += a * mix_w[(16+r)*32 + j];
            }
            d_wr[j] = swr; d_wi[j] = swi;
            if (j == 0) {
                float br = pb[0], bi = 0.f;
                for (int r = 0; r < RR; r++) {
                    float a = rs[r] * pw[r];
                    br += a * mix_b[r];
                    bi += a * mix_b[16+r];
                }
                d_br = br; d_bi = bi;
            }
        }
        return;
    }
    __shared__ float xs[64*65];
    __shared__ float ct[64], st[64];
    __shared__ float ctw[64*36], stw[64*36];  // [w][f0..32]
    const float* p = x + (size_t)(c*16 + l)*4096;
    for (int i = tid; i < 4096; i += 256) xs[(i >> 6)*65 + (i & 63)] = p[i];
    if (tid < 64) sincospif(tid / 32.f, &st[tid], &ct[tid]);
    __syncthreads();
    for (int i = tid; i < 64*33; i += 256) {
        int w = i / 33, f = i % 33;
        int k = (w*f) & 63;
        ctw[w*36 + f] = ct[k]; stw[w*36 + f] = st[k];
    }
    __syncthreads();
    int obase = ((l*32 + c)*33)*64;
    if (tid < 128) {
        int hg = tid >> 3, fg = tid & 7;
        int h0 = hg*4, f0 = fg*4;
        float re[4][4], im[4][4];
        #pragma unroll
        for (int j = 0; j < 4; j++)
            #pragma unroll
            for (int k = 0; k < 4; k++) { re[j][k] = 0.f; im[j][k] = 0.f; }
        for (int w = 0; w < 64; w++) {
            float a0 = xs[(h0+0)*65 + w];
            float a1 = xs[(h0+1)*65 + w];
            float a2 = xs[(h0+2)*65 + w];
            float a3 = xs[(h0+3)*65 + w];
            float cb[4], sb[4];
            #pragma unroll
            for (int k = 0; k < 4; k++) {
                cb[k] = ctw[w*36 + f0 + k];
                sb[k] = stw[w*36 + f0 + k];
            }
            #pragma unroll
            for (int k = 0; k < 4; k++) {
                re[0][k] += a0*cb[k]; im[0][k] -= a0*sb[k];
                re[1][k] += a1*cb[k]; im[1][k] -= a1*sb[k];
                re[2][k] += a2*cb[k]; im[2][k] -= a2*sb[k];
                re[3][k] += a3*cb[k]; im[3][k] -= a3*sb[k];
            }
        }
        #pragma unroll
        for (int k = 0; k < 4; k++)
            #pragma unroll
            for (int j = 0; j < 4; j++) {
                int idx = obase + (f0+k)*64 + h0 + j;
                d_xfr[idx] = re[j][k];
                d_xfi[idx] = im[j][k];
            }
    } else if (tid < 192) {
        int h = tid - 128;
        float s = 0.f;
        #pragma unroll 8
        for (int w = 0; w < 64; w += 2) s += xs[h*65 + w] - xs[h*65 + w + 1];
        d_xfr[obase + 32*64 + h] = s;
        d_xfi[obase + 32*64 + h] = 0.f;
    }
}

// ---------------- glob + adaptive pool + head (coalesced, ff-hoisted) --------
// grid (3 f-chunks of 11, 16 l), block 512 (thread = (c,r)).
// Reads transposed weights d_hwT coalesced; accumulates all 11 ff at once.
__global__ void __launch_bounds__(512)
k_headall(const float* __restrict__ gfc_w, const float* __restrict__ gfc_b,
          const float* __restrict__ head_b, const float* __restrict__ dt)
{
    __shared__ float cm[32];
    __shared__ float gl[32];
    __shared__ float fl[11][32];
    int f0 = blockIdx.x * 11, l = blockIdx.y, tid = threadIdx.x;
    if (tid < 32) {
        float s = 0.f;
        const float* csp = d_cs + (l*32 + tid)*64;
        #pragma unroll 8
        for (int w = 0; w < 64; w++) s += csp[w];
        cm[tid] = s / 4096.f;
    }
    __syncthreads();
    if (tid < 32) {
        float a = gfc_b[tid];
        #pragma unroll
        for (int ci = 0; ci < 32; ci++) a += cm[ci] * gfc_w[tid*32 + ci];
        gl[tid] = fsigmoid(a);
    }
    __syncthreads();
    if (tid < 352) {
        int ff = tid >> 5, cc = tid & 31;
        int fi = f0 + ff;
        int st = (fi*64) / 33;
        int en = ((fi+1)*64 + 32) / 33;
        float s = 0.f;
        for (int k = st; k < en; k++) s += d_cs[(l*32 + cc)*64 + k];
        fl[ff][cc] = gl[cc] * s / (64.f * (float)(en - st));
    }
    __syncthreads();

    int c = tid >> 4, r = tid & 15;
    int row0 = (c*16 + r)*3;
    float p0[11], p1[11], p2[11];
    {
        float b0 = head_b[row0], b1 = head_b[row0+1], b2 = head_b[row0+2];
        #pragma unroll
        for (int ff = 0; ff < 11; ff++) { p0[ff] = b0; p1[ff] = b1; p2[ff] = b2; }
    }
    for (int ci = 0; ci < 32; ci++) {
        const float* hp = d_hwT + ci*1536 + row0;
        float w0 = hp[0], w1 = hp[1], w2 = hp[2];
        #pragma unroll
        for (int ff = 0; ff < 11; ff++) {
            float f = fl[ff][ci];
            p0[ff] += f*w0; p1[ff] += f*w1; p2[ff] += f*w2;
        }
    }
    float dtl = dt[l];
    float g = 1.f - __expf(-2.f * dtl);
    #pragma unroll
    for (int ff = 0; ff < 11; ff++) {
        int fi = f0 + ff;
        float nu = (p0[ff] > 20.f) ? p0[ff] : log1pf(__expf(p0[ff]));
        float decay = __expf(-nu * dtl);
        float ang = tanhf(p1[ff]) * 3.14159265358979323846f * dtl;
        float sa, ca;
        __sincosf(ang, &sa, &ca);
        float sg = fsigmoid(p2[ff]);
        int idx = ((l*32 + c)*33 + fi)*16 + r;
        d_Are[idx] = decay * ca;
        d_Aim[idx] = decay * sa;
        d_S[idx]   = sg * g;
    }
}

// ---------------- scan over L + collapsed mix/proj + pif freq-mix, fused -----
// grid (33 fi, 4 h-groups of 16), block 512 (thread = c*16 + hq).
__global__ void __launch_bounds__(512) k_scanmix(const float* __restrict__ pw)
{
    __shared__ float sAr[512], sAi[512], sS[512];   // [c*16 + r] for current l
    __shared__ float ybr[32*17], ybi[32*17];        // [c*17 + hq]
    __shared__ float wsm[1024];
    __shared__ float swr[32], swi[32];
    int fi = blockIdx.x, hg = blockIdx.y;
    int tid = threadIdx.x;
    int c = tid >> 4, hq = tid & 15;
    int h = hg*16 + hq;
    for (int i = tid; i < 1024; i += 512) wsm[i] = pw[i];
    if (tid < 32) { swr[tid] = d_wr[tid]; swi[tid] = d_wi[tid]; }
    float br = d_br, bi = d_bi;
    float sr[16], si[16];
    #pragma unroll
    for (int r = 0; r < 16; r++) { sr[r] = 0.f; si[r] = 0.f; }

    for (int l = 0; l < 16; l++) {
        {
            int gidx = ((l*32 + (tid >> 4))*33 + fi)*16 + (tid & 15);
            sAr[tid] = d_Are[gidx]; sAi[tid] = d_Aim[gidx]; sS[tid] = d_S[gidx];
        }
        __syncthreads();
        int xidx = ((l*32 + c)*33 + fi)*64 + h;
        float xr = d_xfr[xidx], xi = d_xfi[xidx];
        float yr = br, yi = bi;
        const float* Ar = sAr + c*16;
        const float* Ai = sAi + c*16;
        const float* Ss = sS  + c*16;
        #pragma unroll
        for (int r = 0; r < 16; r++) {
            float ar = Ar[r], ai = Ai[r], s = Ss[r];
            float nr = ar*sr[r] - ai*si[r] + s*xr;
            float ni = ar*si[r] + ai*sr[r] + s*xi;
            sr[r] = nr; si[r] = ni;
            yr += swr[r]*nr + swr[16 + r]*ni;
            yi += swi[r]*nr + swi[16 + r]*ni;
        }
        ybr[c*17 + hq] = yr; ybi[c*17 + hq] = yi;
        __syncthreads();
        float mr = 0.f, mi = 0.f;
        const float* wrow = wsm + c*32;
        #pragma unroll
        for (int c2 = 0; c2 < 32; c2++) {
            float w = wrow[c2];
            mr += w * ybr[c2*17 + hq];
            mi += w * ybi[c2*17 + hq];
        }
        d_xfr[xidx] = mr; d_xfi[xidx] = mi;
        __syncthreads();
    }
}

// ---------------- irfft (33 -> 64) register-tiled + fused reductions ---------
// grid (32 o, 16 l), block 256 = 16 hg x 16 wg, thread 4h x 4w.
__global__ void __launch_bounds__(256) k_irfft(const float* __restrict__ pif_b)
{
    __shared__ float yfr[WF*65], yfi[WF*65];   // [f][h]
    __shared__ float CwT[WF*65], SwT[WF*65];   // [f][w], scale folded
    __shared__ float ys[64*65];                // y tile for reductions
    __shared__ float ct[64], st[64];
    __shared__ float rs1[8], rs2[8];
    int c = blockIdx.x, l = blockIdx.y, tid = threadIdx.x;
    int base = ((l*32 + c)*33)*64;
    for (int i = tid; i < WF*64; i += 256) {
        int f = i >> 6, h = i & 63;
        yfr[f*65 + h] = d_xfr[base + i];
        yfi[f*65 + h] = d_xfi[base + i];
    }
    if (tid < 64) sincospif(tid / 32.f, &st[tid], &ct[tid]);
    __syncthreads();
    for (int i = tid; i < WF*64; i += 256) {
        int f = i >> 6, w = i & 63;
        float scale = (f == 0 || f == 32) ? (1.f/64.f) : (2.f/64.f);
        int k = (f*w) & 63;
        CwT[f*65 + w] = scale * ct[k];
        SwT[f*65 + w] = -scale * st[k];
    }
    __syncthreads();
    float pb = pif_b[c];
    int hg = tid >> 4, wg = tid & 15;
    int h0 = hg*4, w0 = wg*4;
    float acc[4][4];
    #pragma unroll
    for (int j = 0; j < 4; j++)
        #pragma unroll
        for (int k = 0; k < 4; k++) acc[j][k] = pb;
    for (int f = 0; f < WF; f++) {
        float ar[4], ai[4], cb[4], sb[4];
        #pragma unroll
        for (int j = 0; j < 4; j++) {
            ar[j] = yfr[f*65 + h0 + j];
            ai[j] = yfi[f*65 + h0 + j];
        }
        #pragma unroll
        for (int k = 0; k < 4; k++) {
            cb[k] = CwT[f*65 + w0 + k];
            sb[k] = SwT[f*65 + w0 + k];
        }
        #pragma unroll
        for (int j = 0; j < 4; j++)
            #pragma unroll
            for (int k = 0; k < 4; k++)
                acc[j][k] += ar[j]*cb[k] + ai[j]*sb[k];
    }
    float s = 0.f, s2 = 0.f;
    int ob = (l*32 + c)*4096;
    #pragma unroll
    for (int j = 0; j < 4; j++)
        #pragma unroll
        for (int k = 0; k < 4; k++) {
            float v = acc[j][k];
            ys[(h0+j)*65 + w0 + k] = v;
            d_y2[ob + (h0+j)*64 + w0 + k] = v;
            s += v; s2 += v*v;
        }
    int warp = tid >> 5, lane = tid & 31;
    #pragma unroll
    for (int off = 16; off > 0; off >>= 1) {
        s  += __shfl_down_sync(0xffffffffu, s,  off);
        s2 += __shfl_down_sync(0xffffffffu, s2, off);
    }
    if (lane == 0) { rs1[warp] = s; rs2[warp] = s2; }
    __syncthreads();
    if (tid == 0) {
        float t1 = 0.f, t2 = 0.f;
        #pragma unroll
        for (int q = 0; q < 8; q++) { t1 += rs1[q]; t2 += rs2[q]; }
        d_psum[l*32 + c] = t1;
        d_psq [l*32 + c] = t2;
    }
    if (tid < 64) {
        float rsum = 0.f;
        #pragma unroll 8
        for (int w = 0; w < 64; w++) rsum += ys[tid*65 + w];
        d_ymean[(l*32 + c)*64 + tid] = rsum / 64.f;
    }
}

// ---------------- fused groupnorm stats + gate MLP + output ------------------
// grid (16 htiles of 4, 16 l), block 256 (4 h' x 64 w).
__global__ void __launch_bounds__(256)
k_outgate(const float* __restrict__ x,
          const float* __restrict__ gn_w, const float* __restrict__ gn_b,
          const float* __restrict__ g1w, const float* __restrict__ g1b,
          const float* __restrict__ g2w, const float* __restrict__ g2b,
          float* __restrict__ out)
{
    __shared__ float smu[4], srstd[4];
    __shared__ float sym[4][32];
    __shared__ float shid[4][4];
    __shared__ float sgate[4][33];
    int h0 = blockIdx.x * 4, l = blockIdx.y;
    int tid = threadIdx.x;
    if (tid < 4) {
        float s = 0.f, s2 = 0.f;
        #pragma unroll
        for (int c8 = 0; c8 < 8; c8++) {
            s  += d_psum[l*32 + tid*8 + c8];
            s2 += d_psq [l*32 + tid*8 + c8];
        }
        float mu  = s / 32768.f;
        float var = s2 / 32768.f - mu*mu;
        smu[tid] = mu; srstd[tid] = rsqrtf(var + 1e-5f);
    }
    __syncthreads();
    if (tid < 128) {
        int hp = tid >> 5, c = tid & 31;
        int g = c >> 3;
        sym[hp][c] = (d_ymean[(l*32 + c)*64 + h0 + hp] - smu[g]) * srstd[g]
                     * gn_w[c] + gn_b[c];
    }
    __syncthreads();
    if (tid < 16) {
        int hp = tid >> 2, m = tid & 3;
        float a = g1b[m];
        #pragma unroll
        for (int c = 0; c < 32; c++) a += g1w[m*32 + c] * sym[hp][c];
        shid[hp][m] = fsilu(a);
    }
    __syncthreads();
    if (tid < 128) {
        int hp = tid >> 5, c = tid & 31;
        float a = g2b[c];
        #pragma unroll
        for (int m = 0; m < 4; m++) a += g2w[c*4 + m] * shid[hp][m];
        sgate[hp][c] = fsigmoid(a);
    }
    __syncthreads();
    int hp = tid >> 6, w = tid & 63;
    int h = h0 + hp;
    #pragma unroll 4
    for (int c = 0; c < 32; c++) {
        int g = c >> 3;
        float z = (d_y2[((l*32 + c)*64 + h)*64 + w] - smu[g]) * srstd[g]
                  * gn_w[c] + gn_b[c];
        int oidx = ((c*16 + l)*64 + h)*64 + w;
        out[oidx] = x[oidx] + z * sgate[hp][c];
    }
}

// ---------------- launch -----------------------------------------------------
extern "C" void kernel_launch(void* const* d_in, const int* in_sizes, int n_in,
                              void* d_out, int out_size)
{
    const float* x       = (const float*)d_in[0];
    const float* dt      = (const float*)d_in[1];
    const float* conv1_w = (const float*)d_in[2];
    const float* conv1_b = (const float*)d_in[3];
    const float* conv2_w = (const float*)d_in[4];
    const float* conv2_b = (const float*)d_in[5];
    const float* gfc_w   = (const float*)d_in[6];
    const float* gfc_b   = (const float*)d_in[7];
    const float* head_w  = (const float*)d_in[8];
    const float* head_b  = (const float*)d_in[9];
    const float* mix_w   = (const float*)d_in[10];
    const float* mix_b   = (const float*)d_in[11];
    const float* rank_s  = (const float*)d_in[12];
    const float* proj_w  = (const float*)d_in[13];
    const float* proj_b  = (const float*)d_in[14];
    const float* pif_w   = (const float*)d_in[15];
    const float* pif_b   = (const float*)d_in[16];
    const float* gn_w    = (const float*)d_in[17];
    const float* gn_b    = (const float*)d_in[18];
    const float* g1_w    = (const float*)d_in[19];
    const float* g1_b    = (const float*)d_in[20];
    const float* g2_w    = (const float*)d_in[21];
    const float* g2_b    = (const float*)d_in[22];
    float* out = (float*)d_out;

    // 7 launches. Slot 4 (ncu capture) = k_headall (verify the coalescing fix).
    k_rfft<<<dim3(33, 16), 256>>>(x, mix_w, mix_b, rank_s, proj_w, proj_b, head_w);
    k_conv1<<<dim3(16, 16), 256>>>(x, conv1_w, conv1_b);
    k_conv2<<<dim3(16, 16), 256>>>(conv2_w, conv2_b);
    k_headall<<<dim3(3, 16), 512>>>(gfc_w, gfc_b, head_b, dt);
    k_scanmix<<<dim3(33, 4), 512>>>(pif_w);
    k_irfft<<<dim3(32, 16), 256>>>(pif_b);
    k_outgate<<<dim3(16, 16), 256>>>(x, gn_w, gn_b, g1_w, g1_b, g2_w, g2_b, out);
}